// round 5
// baseline (speedup 1.0000x reference)
#include <cuda_runtime.h>
#include <cstdint>
#include <cstddef>

#define T_STEPS 2048
#define BATCH   512
#define HID     33
#define G4      132   // 4*HID gates
#define ODIM    18
#define H1DIM   72

// Scratch: per-layer outputs y[t][b][k] (t-major). 138MB each, static device arrays
// (allocation-free per harness rules).
__device__ float g_y0[(size_t)T_STEPS * BATCH * HID];
__device__ float g_y1[(size_t)T_STEPS * BATCH * HID];

typedef unsigned long long u64;

__device__ __forceinline__ void fma2(u64 &acc, u64 a, u64 b) {
    asm("fma.rn.f32x2 %0, %1, %2, %0;" : "+l"(acc) : "l"(a), "l"(b));
}
__device__ __forceinline__ u64 pack2(float lo, float hi) {
    u64 r; asm("mov.b64 %0, {%1,%2};" : "=l"(r) : "f"(lo), "f"(hi)); return r;
}
__device__ __forceinline__ float2 unpack2(u64 v) {
    float2 r; asm("mov.b64 {%0,%1}, %2;" : "=f"(r.x), "=f"(r.y) : "l"(v)); return r;
}
__device__ __forceinline__ float sigm_(float x) {
    return __fdividef(1.f, 1.f + __expf(-x));
}
__device__ __forceinline__ float tanh_(float x) {
    float e = __expf(2.f * x);
    return 1.f - __fdividef(2.f, e + 1.f);
}

// One CTA = one batch element's full T-step recurrence for one layer.
// Thread j (0..131) owns gate row j (weights register-resident, f32x2-packed over K).
// Threads j<33 additionally own c[j], h[j]. Threads j in [64, 64+IN) prefetch x.
//
// IN:   input width (11 for layer 0, 33 otherwise)
// XBF:  x layout is [B, T, IN] (layer 0) vs [T, B, HID] (y buffers)
// XSRC: -1 = use xin param, 0 = g_y0, 1 = g_y1
// YDST: -1 = no per-step output, 0 = g_y0, 1 = g_y1
template<int IN, bool XBF, int XSRC, int YDST>
__global__ __launch_bounds__(G4)
void lstm_layer_kernel(const float* __restrict__ xin,
                       const float* __restrict__ Wih,
                       const float* __restrict__ Whh,
                       const float* __restrict__ bih,
                       const float* __restrict__ bhh,
                       float* __restrict__ hid)
{
    constexpr int INP = ((IN + 3) / 4) * 4;   // 12 or 36 (zero-padded)
    constexpr int NPI = INP / 2;              // packed pairs for x
    const int b = blockIdx.x;
    const int j = threadIdx.x;

    const float* xp = (XSRC == 0) ? g_y0 : (XSRC == 1) ? g_y1 : xin;
    float* yp = (YDST == 0) ? g_y0 : (YDST == 1) ? g_y1 : nullptr;

    __shared__ __align__(16) float h_sh[36];     // h padded to 36 (tail zero)
    __shared__ __align__(16) float x_sh[INP];    // x_t padded (tail zero)
    __shared__ float g_sh[G4];

    // ---- pack weights into f32x2 registers (once) ----
    u64 whh2[18];
#pragma unroll
    for (int p = 0; p < 18; p++) {
        int m = 2 * p;
        float lo = (m     < HID) ? Whh[j * HID + m]     : 0.f;
        float hi = (m + 1 < HID) ? Whh[j * HID + m + 1] : 0.f;
        whh2[p] = pack2(lo, hi);
    }
    u64 wih2[NPI];
#pragma unroll
    for (int p = 0; p < NPI; p++) {
        int m = 2 * p;
        float lo = (m     < IN) ? Wih[j * IN + m]     : 0.f;
        float hi = (m + 1 < IN) ? Wih[j * IN + m + 1] : 0.f;
        wih2[p] = pack2(lo, hi);
    }
    const float bias = bih[j] + bhh[j];
    const bool is_g  = (j >= 66 && j < 99);   // PyTorch gate order i,f,g,o

    const bool ldr = (j >= 64) && (j < 64 + IN);
    const int  li  = j - 64;

    auto xval = [&](int t, int i) -> float {
        if (XBF) return xp[((size_t)b * T_STEPS + t) * IN + i];
        else     return xp[((size_t)t * BATCH + b) * HID + i];
    };

    // ---- init shared state ----
    if (j < 36) h_sh[j] = 0.f;
    if (j >= IN && j < INP) x_sh[j] = 0.f;
    if (ldr) x_sh[li] = xval(0, li);
    __syncthreads();

    float c  = 0.f;                       // cell state (threads j<33)
    float xr = ldr ? xval(1, li) : 0.f;   // holds x(t+1) entering step t

    for (int t = 0; t < T_STEPS; ++t) {
        // issue depth-2 prefetch of x(t+2) early (long-scoreboard hidden ~1.7 steps)
        float xr2 = 0.f;
        if (ldr && (t + 2) < T_STEPS) xr2 = xval(t + 2, li);

        // gates[j] = bias + Whh[j]·h + Wih[j]·x_t   (two independent f32x2 chains)
        u64 acch = 0ull, accx = 0ull;
        const ulonglong2* hv = (const ulonglong2*)h_sh;
        const ulonglong2* xv = (const ulonglong2*)x_sh;
#pragma unroll
        for (int q = 0; q < 9; q++) {
            ulonglong2 v = hv[q];                 // one LDS.128 -> two packed operands
            fma2(acch, whh2[2 * q],     v.x);
            fma2(acch, whh2[2 * q + 1], v.y);
        }
#pragma unroll
        for (int q = 0; q < INP / 4; q++) {
            ulonglong2 v = xv[q];
            fma2(accx, wih2[2 * q],     v.x);
            fma2(accx, wih2[2 * q + 1], v.y);
        }
        float2 ah = unpack2(acch);
        float2 ax = unpack2(accx);
        float pre = (ah.x + ah.y) + (ax.x + ax.y) + bias;
        float act = is_g ? tanh_(pre) : sigm_(pre);
        g_sh[j] = act;
        __syncthreads();   // B1: gates visible; all h_sh/x_sh reads complete

        if (j < HID) {
            float gi = g_sh[j];
            float gf = g_sh[j + 33];
            float gg = g_sh[j + 66];
            float go = g_sh[j + 99];
            c = gf * c + gi * gg;
            float h = go * tanh_(c);
            h_sh[j] = h;
            if (YDST >= 0) yp[((size_t)t * BATCH + b) * HID + j] = h;
            if (t == T_STEPS - 1) hid[b * HID + j] = h;
        } else if (ldr) {
            x_sh[li] = xr;    // publish x(t+1)
            xr = xr2;         // rotate prefetch
        }
        __syncthreads();   // B2: h_{t}, x_{t+1} ready
    }
}

// MLP head on final hidden states: out = (GELU(hid@W1^T + b1))@W2^T + b2
// One block per row r = l*512 + b (1536 rows).
__global__ __launch_bounds__(H1DIM)
void head_kernel(const float* __restrict__ hid,
                 const float* __restrict__ W1, const float* __restrict__ b1,
                 const float* __restrict__ W2, const float* __restrict__ b2,
                 float* __restrict__ out)
{
    const int r = blockIdx.x;
    const int u = threadIdx.x;
    __shared__ float hrow[HID];
    __shared__ float h1[H1DIM];

    if (u < HID) hrow[u] = hid[r * HID + u];
    __syncthreads();

    float s = b1[u];
#pragma unroll
    for (int m = 0; m < HID; m++) s += W1[u * HID + m] * hrow[m];
    // exact GELU (erf form, matching approximate=False)
    h1[u] = 0.5f * s * (1.f + erff(s * 0.70710678118654752f));
    __syncthreads();

    if (u < ODIM) {
        float s2 = b2[u];
#pragma unroll
        for (int m = 0; m < H1DIM; m++) s2 += W2[u * H1DIM + m] * h1[m];
        out[r * ODIM + u] = s2;
    }
}

extern "C" void kernel_launch(void* const* d_in, const int* in_sizes, int n_in,
                              void* d_out, int out_size)
{
    const float* x    = (const float*)d_in[0];
    const float* Wih0 = (const float*)d_in[1];
    const float* Whh0 = (const float*)d_in[2];
    const float* bih0 = (const float*)d_in[3];
    const float* bhh0 = (const float*)d_in[4];
    const float* Wih1 = (const float*)d_in[5];
    const float* Whh1 = (const float*)d_in[6];
    const float* bih1 = (const float*)d_in[7];
    const float* bhh1 = (const float*)d_in[8];
    const float* Wih2 = (const float*)d_in[9];
    const float* Whh2 = (const float*)d_in[10];
    const float* bih2 = (const float*)d_in[11];
    const float* bhh2 = (const float*)d_in[12];
    const float* W1   = (const float*)d_in[13];
    const float* b1   = (const float*)d_in[14];
    const float* W2   = (const float*)d_in[15];
    const float* b2   = (const float*)d_in[16];

    float* out = (float*)d_out;                      // [3, 512, 18]
    float* hid = out + 3 * BATCH * ODIM;             // [3, 512, 33]

    // layer 0: x [B,T,11] -> y0, hidden row 0
    lstm_layer_kernel<11, true,  -1, 0><<<BATCH, G4>>>(
        x, Wih0, Whh0, bih0, bhh0, hid);
    // layer 1: y0 -> y1, hidden row 1
    lstm_layer_kernel<33, false,  0, 1><<<BATCH, G4>>>(
        nullptr, Wih1, Whh1, bih1, bhh1, hid + BATCH * HID);
    // layer 2: y1 -> (no per-step output), hidden row 2
    lstm_layer_kernel<33, false,  1, -1><<<BATCH, G4>>>(
        nullptr, Wih2, Whh2, bih2, bhh2, hid + 2 * BATCH * HID);
    // MLP head
    head_kernel<<<3 * BATCH, H1DIM>>>(hid, W1, b1, W2, b2, out);
}